// round 5
// baseline (speedup 1.0000x reference)
#include <cuda_runtime.h>
#include <cuda_bf16.h>
#include <math.h>
#include <stdint.h>

typedef unsigned long long ull;

// ---------------- device globals (scratch; no allocations allowed) ----------
__device__ __nv_bfloat16 g_data[8192 * 512]; // bf16 concatenated [source; target]
__device__ float  g_sq[8192];     // per-row squared L2 norms (fp32, from originals)
__device__ float  g_colA[512];    // per-dimension column sums
__device__ double g_sqsum;        // sum of g_sq in double
__device__ double g_acc[4];       // quadrant sums: [XX, XY, YX, YY] as hi*2+hj
__device__ float  g_cc;           // -log2(e) / (bw * 16)  (largest scale)

// ---------------- PTX helpers ----------------------------------------------
__device__ __forceinline__ float ex2f(float x) {
    float y; asm("ex2.approx.ftz.f32 %0, %1;" : "=f"(y) : "f"(x)); return y;
}
__device__ __forceinline__ uint32_t smem_u32(const void* p) {
    uint32_t a;
    asm("{ .reg .u64 t; cvta.to.shared.u64 t, %1; cvt.u32.u64 %0, t; }" : "=r"(a) : "l"(p));
    return a;
}
__device__ __forceinline__ void cp_async16(uint32_t saddr, const void* g) {
    asm volatile("cp.async.cg.shared.global [%0], [%1], 16;" :: "r"(saddr), "l"(g));
}
#define CP_COMMIT()  asm volatile("cp.async.commit_group;" ::: "memory")
#define CP_WAIT2()   asm volatile("cp.async.wait_group 2;" ::: "memory")

__device__ __forceinline__ void ldsm4(uint32_t& r0, uint32_t& r1, uint32_t& r2,
                                      uint32_t& r3, uint32_t addr) {
    asm volatile("ldmatrix.sync.aligned.m8n8.x4.shared.b16 {%0,%1,%2,%3}, [%4];"
                 : "=r"(r0), "=r"(r1), "=r"(r2), "=r"(r3) : "r"(addr));
}
__device__ __forceinline__ void hmma(float* d, const uint32_t* a, uint32_t b0, uint32_t b1) {
    asm volatile(
        "mma.sync.aligned.m16n8k16.row.col.f32.bf16.bf16.f32 "
        "{%0,%1,%2,%3}, {%4,%5,%6,%7}, {%8,%9}, {%0,%1,%2,%3};"
        : "+f"(d[0]), "+f"(d[1]), "+f"(d[2]), "+f"(d[3])
        : "r"(a[0]), "r"(a[1]), "r"(a[2]), "r"(a[3]), "r"(b0), "r"(b1));
}

// ---------------- kernel 0: zero accumulators (graph replays!) --------------
__global__ void k_zero() {
    int t = blockIdx.x * blockDim.x + threadIdx.x;
    if (t < 512) g_colA[t] = 0.f;
    if (t == 0) {
        g_sqsum = 0.0;
        g_acc[0] = g_acc[1] = g_acc[2] = g_acc[3] = 0.0;
    }
}

// ---------------- kernel 1: fused prep: bf16 convert + row sq + col sums ----
__global__ __launch_bounds__(256)
void k_prep(const float* __restrict__ src, const float* __restrict__ tgt) {
    __shared__ float scol[512];
    __shared__ double ssq[8];
    int tid = threadIdx.x, w = tid >> 5, lane = tid & 31;

    for (int i = tid; i < 512; i += 256) scol[i] = 0.f;

    float colacc[16];
#pragma unroll
    for (int i = 0; i < 16; i++) colacc[i] = 0.f;

    double warp_sq = 0.0;
    __syncthreads();

#pragma unroll
    for (int rr = 0; rr < 4; rr++) {
        int row = blockIdx.x * 32 + w * 4 + rr;
        const float* p = (row < 4096) ? src + (size_t)row * 512
                                      : tgt + (size_t)(row - 4096) * 512;
        float s = 0.f;
#pragma unroll
        for (int c = 0; c < 4; c++) {
            float4 v = *(const float4*)(p + lane * 4 + c * 128);
            uint2 o;
            asm("cvt.rn.bf16x2.f32 %0, %1, %2;" : "=r"(o.x) : "f"(v.y), "f"(v.x));
            asm("cvt.rn.bf16x2.f32 %0, %1, %2;" : "=r"(o.y) : "f"(v.w), "f"(v.z));
            *(uint2*)(g_data + (size_t)row * 512 + lane * 4 + c * 128) = o;
            s = fmaf(v.x, v.x, s); s = fmaf(v.y, v.y, s);
            s = fmaf(v.z, v.z, s); s = fmaf(v.w, v.w, s);
            colacc[c * 4 + 0] += v.x; colacc[c * 4 + 1] += v.y;
            colacc[c * 4 + 2] += v.z; colacc[c * 4 + 3] += v.w;
        }
#pragma unroll
        for (int o = 16; o; o >>= 1) s += __shfl_xor_sync(0xffffffffu, s, o);
        if (lane == 0) { g_sq[row] = s; warp_sq += (double)s; }
    }

#pragma unroll
    for (int c = 0; c < 4; c++)
#pragma unroll
        for (int j = 0; j < 4; j++)
            atomicAdd(&scol[lane * 4 + c * 128 + j], colacc[c * 4 + j]);
    if (lane == 0) ssq[w] = warp_sq;
    __syncthreads();

    for (int i = tid; i < 512; i += 256) atomicAdd(&g_colA[i], scol[i]);
    if (tid == 0) {
        double t = 0;
        for (int i = 0; i < 8; i++) t += ssq[i];
        atomicAdd(&g_sqsum, t);
    }
}

// ---------------- kernel 2: bandwidth -> single exp coefficient -------------
__global__ void k_scale() {
    __shared__ double red[512];
    int t = threadIdx.x;
    double c = (double)g_colA[t];
    red[t] = c * c;
    __syncthreads();
    for (int o = 256; o; o >>= 1) { if (t < o) red[t] += red[t + o]; __syncthreads(); }
    if (t == 0) {
        double n = 8192.0;
        double sum_l2 = 2.0 * n * g_sqsum - 2.0 * red[0];
        double bw = sum_l2 / (n * n - n);
        bw /= 4.0;  // KERNEL_MUL ** (KERNEL_NUM // 2)
        const double LOG2E = 1.4426950408889634;
        g_cc = (float)(-LOG2E / (bw * 16.0));
    }
}

// ---------------- kernel 3: mma.sync bf16 GEMM + fused epilogue -------------
// CTA tile 128x256; super-tiles 256x256 triangular over 32x32 -> 528*2 = 1056 CTAs.
// 8 warps (2m x 4n), warp tile 64x64. K=512 in 16 chunks of 32, 4-stage cp.async.
static constexpr int KT = 16;
static constexpr int A_BYTES = 8192;        // 128 rows x 64B
static constexpr int STAGE_BYTES = 24576;   // A 8KB + B 16KB (256 rows x 64B)
static constexpr int SMEM_TOTAL = 4 * STAGE_BYTES;  // 98304

__global__ __launch_bounds__(256, 1)
void k_mma() {
    extern __shared__ char sm[];
    uint32_t sbase = smem_u32(sm);

    int tid = threadIdx.x;
    int wid = tid >> 5, lane = tid & 31;

    // super-tile decode: sx = J*(J+1)/2 + I, I <= J over 32 blocks of 256
    int sx = blockIdx.x >> 1, half = blockIdx.x & 1;
    int J = (int)((sqrtf(8.0f * (float)sx + 1.0f) - 1.0f) * 0.5f);
    while ((J + 1) * (J + 2) / 2 <= sx) J++;
    while (J * (J + 1) / 2 > sx) J--;
    int I = sx - J * (J + 1) / 2;
    int rowA = I * 256 + half * 128;   // 128 rows
    int rowB = J * 256;                // 256 cols

    // ---- stage loader: 1536 x 16B per stage, 6 per thread --------------------
    auto load_stage = [&](int kt, int slot) {
#pragma unroll
        for (int i = 0; i < 6; i++) {
            int t = tid + i * 256;
            int isA = (t < 512);
            int u = isA ? t : (t - 512);
            int r = u >> 2;
            int c16 = u & 3;
            int grow = (isA ? rowA : rowB) + r;
            const __nv_bfloat16* gp = g_data + (size_t)grow * 512 + kt * 32 + c16 * 8;
            uint32_t off = r * 64 + ((c16 ^ (r & 3)) << 4);
            uint32_t sa = sbase + slot * STAGE_BYTES + (isA ? 0 : A_BYTES) + off;
            cp_async16(sa, gp);
        }
        CP_COMMIT();
    };

    load_stage(0, 0);
    load_stage(1, 1);
    load_stage(2, 2);

    int wm = (wid >> 2) * 64;   // warp m offset (0 or 64)
    int wn = (wid & 3) * 64;    // warp n offset (0,64,128,192)

    // ldmatrix lane decomposition
    int mat = lane >> 3, r8 = lane & 7;
    int lrow = (mat & 1) * 8 + r8;
    int lhi  = mat >> 1;

    // precompute ldmatrix offsets (relative to stage base)
    uint32_t aoff[2][4], boff[2][4];
#pragma unroll
    for (int ks = 0; ks < 2; ks++) {
        int c16 = ks * 2 + lhi;
#pragma unroll
        for (int mt = 0; mt < 4; mt++) {
            int m = wm + mt * 16 + lrow;
            aoff[ks][mt] = m * 64 + ((c16 ^ (m & 3)) << 4);
        }
#pragma unroll
        for (int g = 0; g < 4; g++) {
            int n = wn + g * 16 + lrow;
            boff[ks][g] = A_BYTES + n * 64 + ((c16 ^ (n & 3)) << 4);
        }
    }

    float acc[4][8][4];
#pragma unroll
    for (int a = 0; a < 4; a++)
#pragma unroll
        for (int b = 0; b < 8; b++)
#pragma unroll
            for (int c = 0; c < 4; c++) acc[a][b][c] = 0.f;

    for (int kt = 0; kt < KT; kt++) {
        int slot = kt & 3;
        CP_WAIT2();
        __syncthreads();
        if (kt + 3 < KT) load_stage(kt + 3, (kt + 3) & 3);
        else { CP_COMMIT(); }

        uint32_t stg = sbase + slot * STAGE_BYTES;

#pragma unroll
        for (int ks = 0; ks < 2; ks++) {
            uint32_t af[4][4], bf[4][4];
#pragma unroll
            for (int mt = 0; mt < 4; mt++)
                ldsm4(af[mt][0], af[mt][1], af[mt][2], af[mt][3], stg + aoff[ks][mt]);
#pragma unroll
            for (int g = 0; g < 4; g++)
                ldsm4(bf[g][0], bf[g][1], bf[g][2], bf[g][3], stg + boff[ks][g]);
#pragma unroll
            for (int mt = 0; mt < 4; mt++)
#pragma unroll
                for (int nt = 0; nt < 8; nt++)
                    hmma(acc[mt][nt], af[mt],
                         bf[nt >> 1][nt & 1], bf[nt >> 1][(nt & 1) + 2]);
        }
        __syncthreads();
    }

    // ---- epilogue ------------------------------------------------------------
    float* s_sq = (float*)sm;          // [0:128)=A rows, [128:384)=B rows
    for (int i = tid; i < 384; i += 256)
        s_sq[i] = (i < 128) ? g_sq[rowA + i] : g_sq[rowB + i - 128];
    __syncthreads();

    float cc = g_cc;
    int er = lane >> 2, ec = (lane & 3) * 2;
    double dsum = 0.0;
#pragma unroll
    for (int mt = 0; mt < 4; mt++) {
        float sqi0 = s_sq[wm + mt * 16 + er];
        float sqi1 = s_sq[wm + mt * 16 + er + 8];
#pragma unroll
        for (int nt = 0; nt < 8; nt++) {
            float sqj0 = s_sq[128 + wn + nt * 8 + ec];
            float sqj1 = s_sq[128 + wn + nt * 8 + ec + 1];
            float d0 = acc[mt][nt][0], d1 = acc[mt][nt][1];
            float d2 = acc[mt][nt][2], d3 = acc[mt][nt][3];
            float l0 = fmaxf(fmaf(-2.f, d0, sqi0 + sqj0), 0.f);
            float l1 = fmaxf(fmaf(-2.f, d1, sqi0 + sqj1), 0.f);
            float l2 = fmaxf(fmaf(-2.f, d2, sqi1 + sqj0), 0.f);
            float l3 = fmaxf(fmaf(-2.f, d3, sqi1 + sqj1), 0.f);
            float t0 = ex2f(l0 * cc), t1 = ex2f(l1 * cc);
            float t2 = ex2f(l2 * cc), t3 = ex2f(l3 * cc);
            float fs = 0.f;
            {
                float a2 = t0 * t0, a4 = a2 * a2, a8 = a4 * a4;
                fs += ((t0 + a2) + (a4 + a8)) + a8 * a8;
            }
            {
                float a2 = t1 * t1, a4 = a2 * a2, a8 = a4 * a4;
                fs += ((t1 + a2) + (a4 + a8)) + a8 * a8;
            }
            {
                float a2 = t2 * t2, a4 = a2 * a2, a8 = a4 * a4;
                fs += ((t2 + a2) + (a4 + a8)) + a8 * a8;
            }
            {
                float a2 = t3 * t3, a4 = a2 * a2, a8 = a4 * a4;
                fs += ((t3 + a2) + (a4 + a8)) + a8 * a8;
            }
            dsum += (double)fs;
        }
    }

    // block reduce doubles in smem
    __syncthreads();
    double* red = (double*)sm;
    red[tid] = dsum;
    __syncthreads();
    for (int o = 128; o; o >>= 1) { if (tid < o) red[tid] += red[tid + o]; __syncthreads(); }
    if (tid == 0) {
        int hi = (rowA >= 4096), hj = (rowB >= 4096);
        atomicAdd(&g_acc[hi * 2 + hj], red[0]);
        if (I != J) atomicAdd(&g_acc[hj * 2 + hi], red[0]);
    }
}

// ---------------- kernel 4: final scalar ------------------------------------
__global__ void k_final(float* __restrict__ out) {
    double inv = 1.0 / (4096.0 * 4096.0);
    out[0] = (float)((g_acc[0] + g_acc[3] - g_acc[1] - g_acc[2]) * inv);
}

// ---------------- launcher ---------------------------------------------------
extern "C" void kernel_launch(void* const* d_in, const int* in_sizes, int n_in,
                              void* d_out, int out_size) {
    const float* src = (const float*)d_in[0];
    const float* tgt = (const float*)d_in[1];
    float* out = (float*)d_out;

    cudaFuncSetAttribute(k_mma, cudaFuncAttributeMaxDynamicSharedMemorySize, SMEM_TOTAL);

    k_zero<<<2, 256>>>();
    k_prep<<<256, 256>>>(src, tgt);
    k_scale<<<1, 512>>>();
    k_mma<<<1056, 256, SMEM_TOTAL>>>();
    k_final<<<1, 1>>>(out);
}

// round 6
// speedup vs baseline: 1.2556x; 1.2556x over previous
#include <cuda_runtime.h>
#include <cuda_bf16.h>
#include <math.h>
#include <stdint.h>

typedef unsigned long long ull;

// ---------------- device globals (scratch; no allocations allowed) ----------
__device__ __nv_bfloat16 g_data[8192 * 512]; // bf16 concatenated [source; target]
__device__ float  g_sq[8192];     // per-row squared L2 norms (fp32, from originals)
__device__ float  g_colA[512];    // per-dimension column sums
__device__ double g_sqsum;        // sum of g_sq in double
__device__ double g_acc[4];       // quadrant sums: [XX, XY, YX, YY] as hi*2+hj
__device__ float  g_cc;           // -log2(e) / (bw * 16)  (largest scale)

// ---------------- PTX helpers ----------------------------------------------
__device__ __forceinline__ float ex2f(float x) {
    float y; asm("ex2.approx.ftz.f32 %0, %1;" : "=f"(y) : "f"(x)); return y;
}
__device__ __forceinline__ uint32_t smem_u32(const void* p) {
    uint32_t a;
    asm("{ .reg .u64 t; cvta.to.shared.u64 t, %1; cvt.u32.u64 %0, t; }" : "=r"(a) : "l"(p));
    return a;
}
__device__ __forceinline__ void cp_async16(uint32_t saddr, const void* g) {
    asm volatile("cp.async.cg.shared.global [%0], [%1], 16;" :: "r"(saddr), "l"(g));
}
#define CP_COMMIT()  asm volatile("cp.async.commit_group;" ::: "memory")
#define CP_WAIT2()   asm volatile("cp.async.wait_group 2;" ::: "memory")

__device__ __forceinline__ void ldsm4(uint32_t& r0, uint32_t& r1, uint32_t& r2,
                                      uint32_t& r3, uint32_t addr) {
    asm volatile("ldmatrix.sync.aligned.m8n8.x4.shared.b16 {%0,%1,%2,%3}, [%4];"
                 : "=r"(r0), "=r"(r1), "=r"(r2), "=r"(r3) : "r"(addr));
}
__device__ __forceinline__ void hmma(float* d, const uint32_t* a, uint32_t b0, uint32_t b1) {
    asm volatile(
        "mma.sync.aligned.m16n8k16.row.col.f32.bf16.bf16.f32 "
        "{%0,%1,%2,%3}, {%4,%5,%6,%7}, {%8,%9}, {%0,%1,%2,%3};"
        : "+f"(d[0]), "+f"(d[1]), "+f"(d[2]), "+f"(d[3])
        : "r"(a[0]), "r"(a[1]), "r"(a[2]), "r"(a[3]), "r"(b0), "r"(b1));
}

// ---------------- kernel 0: zero accumulators (graph replays!) --------------
__global__ void k_zero() {
    int t = blockIdx.x * blockDim.x + threadIdx.x;
    if (t < 512) g_colA[t] = 0.f;
    if (t == 0) {
        g_sqsum = 0.0;
        g_acc[0] = g_acc[1] = g_acc[2] = g_acc[3] = 0.0;
    }
}

// ---------------- kernel 1: fused prep: bf16 convert + row sq + col sums ----
__global__ __launch_bounds__(256)
void k_prep(const float* __restrict__ src, const float* __restrict__ tgt) {
    __shared__ float scol[512];
    __shared__ double ssq[8];
    int tid = threadIdx.x, w = tid >> 5, lane = tid & 31;

    for (int i = tid; i < 512; i += 256) scol[i] = 0.f;

    float colacc[16];
#pragma unroll
    for (int i = 0; i < 16; i++) colacc[i] = 0.f;

    double warp_sq = 0.0;
    __syncthreads();

#pragma unroll
    for (int rr = 0; rr < 4; rr++) {
        int row = blockIdx.x * 32 + w * 4 + rr;
        const float* p = (row < 4096) ? src + (size_t)row * 512
                                      : tgt + (size_t)(row - 4096) * 512;
        float s = 0.f;
#pragma unroll
        for (int c = 0; c < 4; c++) {
            float4 v = *(const float4*)(p + lane * 4 + c * 128);
            uint2 o;
            asm("cvt.rn.bf16x2.f32 %0, %1, %2;" : "=r"(o.x) : "f"(v.y), "f"(v.x));
            asm("cvt.rn.bf16x2.f32 %0, %1, %2;" : "=r"(o.y) : "f"(v.w), "f"(v.z));
            *(uint2*)(g_data + (size_t)row * 512 + lane * 4 + c * 128) = o;
            s = fmaf(v.x, v.x, s); s = fmaf(v.y, v.y, s);
            s = fmaf(v.z, v.z, s); s = fmaf(v.w, v.w, s);
            colacc[c * 4 + 0] += v.x; colacc[c * 4 + 1] += v.y;
            colacc[c * 4 + 2] += v.z; colacc[c * 4 + 3] += v.w;
        }
#pragma unroll
        for (int o = 16; o; o >>= 1) s += __shfl_xor_sync(0xffffffffu, s, o);
        if (lane == 0) { g_sq[row] = s; warp_sq += (double)s; }
    }

#pragma unroll
    for (int c = 0; c < 4; c++)
#pragma unroll
        for (int j = 0; j < 4; j++)
            atomicAdd(&scol[lane * 4 + c * 128 + j], colacc[c * 4 + j]);
    if (lane == 0) ssq[w] = warp_sq;
    __syncthreads();

    for (int i = tid; i < 512; i += 256) atomicAdd(&g_colA[i], scol[i]);
    if (tid == 0) {
        double t = 0;
        for (int i = 0; i < 8; i++) t += ssq[i];
        atomicAdd(&g_sqsum, t);
    }
}

// ---------------- kernel 2: bandwidth -> single exp coefficient -------------
__global__ void k_scale() {
    __shared__ double red[512];
    int t = threadIdx.x;
    double c = (double)g_colA[t];
    red[t] = c * c;
    __syncthreads();
    for (int o = 256; o; o >>= 1) { if (t < o) red[t] += red[t + o]; __syncthreads(); }
    if (t == 0) {
        double n = 8192.0;
        double sum_l2 = 2.0 * n * g_sqsum - 2.0 * red[0];
        double bw = sum_l2 / (n * n - n);
        bw /= 4.0;  // KERNEL_MUL ** (KERNEL_NUM // 2)
        const double LOG2E = 1.4426950408889634;
        g_cc = (float)(-LOG2E / (bw * 16.0));
    }
}

// ---------------- kernel 3: mma.sync bf16 GEMM + fused epilogue -------------
// CTA tile 128x128, triangular over 64x64 blocks -> 2080 CTAs.
// 4 warps (2m x 2n), warp tile 64x64, 128 threads. 2 CTAs/SM.
// K=512 in 16 chunks of 32, 4-stage cp.async, single barrier per chunk.
static constexpr int KT = 16;
static constexpr int A_BYTES = 8192;        // 128 rows x 64B
static constexpr int STAGE_BYTES = 16384;   // A 8KB + B 8KB
static constexpr int SMEM_TOTAL = 4 * STAGE_BYTES;  // 65536

__global__ __launch_bounds__(128, 2)
void k_mma() {
    extern __shared__ char sm[];
    uint32_t sbase = smem_u32(sm);

    int tid = threadIdx.x;
    int wid = tid >> 5, lane = tid & 31;

    // triangular block decode: idx = bj*(bj+1)/2 + bi, bi <= bj (64 blocks)
    int idx = blockIdx.x;
    int bj = (int)((sqrtf(8.0f * (float)idx + 1.0f) - 1.0f) * 0.5f);
    while ((bj + 1) * (bj + 2) / 2 <= idx) bj++;
    while (bj * (bj + 1) / 2 > idx) bj--;
    int bi = idx - bj * (bj + 1) / 2;
    int rowA = bi * 128, rowB = bj * 128;

    // ---- stage loader: 1024 x 16B per stage, 8 per thread --------------------
    auto load_stage = [&](int kt, int slot) {
#pragma unroll
        for (int i = 0; i < 8; i++) {
            int t = tid + i * 128;
            int isA = (t < 512);
            int u = isA ? t : (t - 512);
            int r = u >> 2;
            int c16 = u & 3;
            int grow = (isA ? rowA : rowB) + r;
            const __nv_bfloat16* gp = g_data + (size_t)grow * 512 + kt * 32 + c16 * 8;
            uint32_t off = r * 64 + ((c16 ^ (r & 3)) << 4);
            uint32_t sa = sbase + slot * STAGE_BYTES + (isA ? 0 : A_BYTES) + off;
            cp_async16(sa, gp);
        }
        CP_COMMIT();
    };

    load_stage(0, 0);
    load_stage(1, 1);
    load_stage(2, 2);

    int wm = (wid >> 1) * 64;   // warp m offset (0 or 64)
    int wn = (wid & 1) * 64;    // warp n offset (0 or 64)

    // ldmatrix lane decomposition
    int mat = lane >> 3, r8 = lane & 7;
    int lrow = (mat & 1) * 8 + r8;
    int lhi  = mat >> 1;

    // precompute ldmatrix offsets (relative to stage base)
    uint32_t aoff[2][4], boff[2][4];
#pragma unroll
    for (int ks = 0; ks < 2; ks++) {
        int c16 = ks * 2 + lhi;
#pragma unroll
        for (int mt = 0; mt < 4; mt++) {
            int m = wm + mt * 16 + lrow;
            aoff[ks][mt] = m * 64 + ((c16 ^ (m & 3)) << 4);
        }
#pragma unroll
        for (int g = 0; g < 4; g++) {
            int n = wn + g * 16 + lrow;
            boff[ks][g] = A_BYTES + n * 64 + ((c16 ^ (n & 3)) << 4);
        }
    }

    float acc[4][8][4];
#pragma unroll
    for (int a = 0; a < 4; a++)
#pragma unroll
        for (int b = 0; b < 8; b++)
#pragma unroll
            for (int c = 0; c < 4; c++) acc[a][b][c] = 0.f;

    for (int kt = 0; kt < KT; kt++) {
        int slot = kt & 3;
        CP_WAIT2();
        __syncthreads();            // single barrier per chunk (slot-distance safe)
        if (kt + 3 < KT) load_stage(kt + 3, (kt + 3) & 3);
        else { CP_COMMIT(); }

        uint32_t stg = sbase + slot * STAGE_BYTES;

#pragma unroll
        for (int ks = 0; ks < 2; ks++) {
            uint32_t af[4][4], bf[4][4];
#pragma unroll
            for (int mt = 0; mt < 4; mt++)
                ldsm4(af[mt][0], af[mt][1], af[mt][2], af[mt][3], stg + aoff[ks][mt]);
#pragma unroll
            for (int g = 0; g < 4; g++)
                ldsm4(bf[g][0], bf[g][1], bf[g][2], bf[g][3], stg + boff[ks][g]);
#pragma unroll
            for (int mt = 0; mt < 4; mt++)
#pragma unroll
                for (int nt = 0; nt < 8; nt++)
                    hmma(acc[mt][nt], af[mt],
                         bf[nt >> 1][nt & 1], bf[nt >> 1][(nt & 1) + 2]);
        }
    }
    __syncthreads();   // all compute done before epilogue reuses smem

    // ---- epilogue ------------------------------------------------------------
    float* s_sq = (float*)sm;          // [0:128)=A rows, [128:256)=B rows
    s_sq[tid] = g_sq[rowA + tid];
    s_sq[tid + 128] = g_sq[rowB + tid];
    __syncthreads();

    float cc = g_cc;
    int er = lane >> 2, ec = (lane & 3) * 2;
    double dsum = 0.0;
#pragma unroll
    for (int mt = 0; mt < 4; mt++) {
        float sqi0 = s_sq[wm + mt * 16 + er];
        float sqi1 = s_sq[wm + mt * 16 + er + 8];
#pragma unroll
        for (int nt = 0; nt < 8; nt++) {
            float sqj0 = s_sq[128 + wn + nt * 8 + ec];
            float sqj1 = s_sq[128 + wn + nt * 8 + ec + 1];
            float d0 = acc[mt][nt][0], d1 = acc[mt][nt][1];
            float d2 = acc[mt][nt][2], d3 = acc[mt][nt][3];
            float l0 = fmaxf(fmaf(-2.f, d0, sqi0 + sqj0), 0.f);
            float l1 = fmaxf(fmaf(-2.f, d1, sqi0 + sqj1), 0.f);
            float l2 = fmaxf(fmaf(-2.f, d2, sqi1 + sqj0), 0.f);
            float l3 = fmaxf(fmaf(-2.f, d3, sqi1 + sqj1), 0.f);
            float t0 = ex2f(l0 * cc), t1 = ex2f(l1 * cc);
            float t2 = ex2f(l2 * cc), t3 = ex2f(l3 * cc);
            float fs = 0.f;
            {
                float a2 = t0 * t0, a4 = a2 * a2, a8 = a4 * a4;
                fs += ((t0 + a2) + (a4 + a8)) + a8 * a8;
            }
            {
                float a2 = t1 * t1, a4 = a2 * a2, a8 = a4 * a4;
                fs += ((t1 + a2) + (a4 + a8)) + a8 * a8;
            }
            {
                float a2 = t2 * t2, a4 = a2 * a2, a8 = a4 * a4;
                fs += ((t2 + a2) + (a4 + a8)) + a8 * a8;
            }
            {
                float a2 = t3 * t3, a4 = a2 * a2, a8 = a4 * a4;
                fs += ((t3 + a2) + (a4 + a8)) + a8 * a8;
            }
            dsum += (double)fs;
        }
    }

    // block reduce doubles in smem
    __syncthreads();
    double* red = (double*)sm;
    red[tid] = dsum;
    __syncthreads();
    for (int o = 64; o; o >>= 1) { if (tid < o) red[tid] += red[tid + o]; __syncthreads(); }
    if (tid == 0) {
        int hi = (bi >= 32), hj = (bj >= 32);
        atomicAdd(&g_acc[hi * 2 + hj], red[0]);
        if (bi != bj) atomicAdd(&g_acc[hj * 2 + hi], red[0]);
    }
}

// ---------------- kernel 4: final scalar ------------------------------------
__global__ void k_final(float* __restrict__ out) {
    double inv = 1.0 / (4096.0 * 4096.0);
    out[0] = (float)((g_acc[0] + g_acc[3] - g_acc[1] - g_acc[2]) * inv);
}

// ---------------- launcher ---------------------------------------------------
extern "C" void kernel_launch(void* const* d_in, const int* in_sizes, int n_in,
                              void* d_out, int out_size) {
    const float* src = (const float*)d_in[0];
    const float* tgt = (const float*)d_in[1];
    float* out = (float*)d_out;

    cudaFuncSetAttribute(k_mma, cudaFuncAttributeMaxDynamicSharedMemorySize, SMEM_TOTAL);

    k_zero<<<2, 256>>>();
    k_prep<<<256, 256>>>(src, tgt);
    k_scale<<<1, 512>>>();
    k_mma<<<2080, 128, SMEM_TOTAL>>>();
    k_final<<<1, 1>>>(out);
}

// round 7
// speedup vs baseline: 1.4542x; 1.1582x over previous
#include <cuda_runtime.h>
#include <cuda_bf16.h>
#include <math.h>
#include <stdint.h>

typedef unsigned long long ull;

// ---------------- device globals (scratch; no allocations allowed) ----------
__device__ __nv_bfloat16 g_data[8192 * 512]; // bf16 concatenated [source; target]
__device__ float  g_sq[8192];     // per-row squared L2 norms (fp32, from originals)
__device__ float  g_colA[512];    // per-dimension column sums
__device__ double g_sqsum;        // sum of g_sq in double
__device__ double g_acc[4];       // quadrant sums: [XX, XY, YX, YY] as hi*2+hj
__device__ float  g_cc;           // -log2(e) / (bw * 16)  (largest scale)

// ---------------- PTX helpers ----------------------------------------------
__device__ __forceinline__ float ex2f(float x) {
    float y; asm("ex2.approx.ftz.f32 %0, %1;" : "=f"(y) : "f"(x)); return y;
}
__device__ __forceinline__ uint32_t smem_u32(const void* p) {
    uint32_t a;
    asm("{ .reg .u64 t; cvta.to.shared.u64 t, %1; cvt.u32.u64 %0, t; }" : "=r"(a) : "l"(p));
    return a;
}
__device__ __forceinline__ void cp_async16(uint32_t saddr, const void* g) {
    asm volatile("cp.async.cg.shared.global [%0], [%1], 16;" :: "r"(saddr), "l"(g));
}
#define CP_COMMIT()  asm volatile("cp.async.commit_group;" ::: "memory")
#define CP_WAIT1()   asm volatile("cp.async.wait_group 1;" ::: "memory")

__device__ __forceinline__ void ldsm4(uint32_t& r0, uint32_t& r1, uint32_t& r2,
                                      uint32_t& r3, uint32_t addr) {
    asm volatile("ldmatrix.sync.aligned.m8n8.x4.shared.b16 {%0,%1,%2,%3}, [%4];"
                 : "=r"(r0), "=r"(r1), "=r"(r2), "=r"(r3) : "r"(addr));
}
__device__ __forceinline__ void hmma(float* d, const uint32_t* a, uint32_t b0, uint32_t b1) {
    asm volatile(
        "mma.sync.aligned.m16n8k16.row.col.f32.bf16.bf16.f32 "
        "{%0,%1,%2,%3}, {%4,%5,%6,%7}, {%8,%9}, {%0,%1,%2,%3};"
        : "+f"(d[0]), "+f"(d[1]), "+f"(d[2]), "+f"(d[3])
        : "r"(a[0]), "r"(a[1]), "r"(a[2]), "r"(a[3]), "r"(b0), "r"(b1));
}

// ---------------- kernel 0: zero accumulators (graph replays!) --------------
__global__ void k_zero() {
    int t = blockIdx.x * blockDim.x + threadIdx.x;
    if (t < 512) g_colA[t] = 0.f;
    if (t == 0) {
        g_sqsum = 0.0;
        g_acc[0] = g_acc[1] = g_acc[2] = g_acc[3] = 0.0;
    }
}

// ---------------- kernel 1: fused prep: bf16 convert + row sq + col sums ----
__global__ __launch_bounds__(256)
void k_prep(const float* __restrict__ src, const float* __restrict__ tgt) {
    __shared__ float scol[512];
    __shared__ double ssq[8];
    int tid = threadIdx.x, w = tid >> 5, lane = tid & 31;

    for (int i = tid; i < 512; i += 256) scol[i] = 0.f;

    float colacc[16];
#pragma unroll
    for (int i = 0; i < 16; i++) colacc[i] = 0.f;

    double warp_sq = 0.0;
    __syncthreads();

#pragma unroll
    for (int rr = 0; rr < 4; rr++) {
        int row = blockIdx.x * 32 + w * 4 + rr;
        const float* p = (row < 4096) ? src + (size_t)row * 512
                                      : tgt + (size_t)(row - 4096) * 512;
        float s = 0.f;
#pragma unroll
        for (int c = 0; c < 4; c++) {
            float4 v = *(const float4*)(p + lane * 4 + c * 128);
            uint2 o;
            asm("cvt.rn.bf16x2.f32 %0, %1, %2;" : "=r"(o.x) : "f"(v.y), "f"(v.x));
            asm("cvt.rn.bf16x2.f32 %0, %1, %2;" : "=r"(o.y) : "f"(v.w), "f"(v.z));
            *(uint2*)(g_data + (size_t)row * 512 + lane * 4 + c * 128) = o;
            s = fmaf(v.x, v.x, s); s = fmaf(v.y, v.y, s);
            s = fmaf(v.z, v.z, s); s = fmaf(v.w, v.w, s);
            colacc[c * 4 + 0] += v.x; colacc[c * 4 + 1] += v.y;
            colacc[c * 4 + 2] += v.z; colacc[c * 4 + 3] += v.w;
        }
#pragma unroll
        for (int o = 16; o; o >>= 1) s += __shfl_xor_sync(0xffffffffu, s, o);
        if (lane == 0) { g_sq[row] = s; warp_sq += (double)s; }
    }

#pragma unroll
    for (int c = 0; c < 4; c++)
#pragma unroll
        for (int j = 0; j < 4; j++)
            atomicAdd(&scol[lane * 4 + c * 128 + j], colacc[c * 4 + j]);
    if (lane == 0) ssq[w] = warp_sq;
    __syncthreads();

    for (int i = tid; i < 512; i += 256) atomicAdd(&g_colA[i], scol[i]);
    if (tid == 0) {
        double t = 0;
        for (int i = 0; i < 8; i++) t += ssq[i];
        atomicAdd(&g_sqsum, t);
    }
}

// ---------------- kernel 2: bandwidth -> single exp coefficient -------------
__global__ void k_scale() {
    __shared__ double red[512];
    int t = threadIdx.x;
    double c = (double)g_colA[t];
    red[t] = c * c;
    __syncthreads();
    for (int o = 256; o; o >>= 1) { if (t < o) red[t] += red[t + o]; __syncthreads(); }
    if (t == 0) {
        double n = 8192.0;
        double sum_l2 = 2.0 * n * g_sqsum - 2.0 * red[0];
        double bw = sum_l2 / (n * n - n);
        bw /= 4.0;  // KERNEL_MUL ** (KERNEL_NUM // 2)
        const double LOG2E = 1.4426950408889634;
        g_cc = (float)(-LOG2E / (bw * 16.0));
    }
}

// ---------------- kernel 3: mma.sync bf16 GEMM + fused epilogue -------------
// CTA tile 128x128, triangular over 64x64 blocks -> 2080 CTAs.
// 4 warps (2m x 2n), warp tile 64x64, 128 threads. 2 CTAs/SM.
// K=512 in 8 chunks of 64 (4 ks phases each), 3-stage cp.async pipeline.
static constexpr int KT = 8;
static constexpr int A_BYTES = 16384;       // 128 rows x 128B
static constexpr int STAGE_BYTES = 32768;   // A 16KB + B 16KB
static constexpr int SMEM_TOTAL = 3 * STAGE_BYTES;  // 98304

__global__ __launch_bounds__(128, 2)
void k_mma() {
    extern __shared__ char sm[];
    uint32_t sbase = smem_u32(sm);

    int tid = threadIdx.x;
    int wid = tid >> 5, lane = tid & 31;

    // triangular block decode: idx = bj*(bj+1)/2 + bi, bi <= bj (64 blocks)
    int idx = blockIdx.x;
    int bj = (int)((sqrtf(8.0f * (float)idx + 1.0f) - 1.0f) * 0.5f);
    while ((bj + 1) * (bj + 2) / 2 <= idx) bj++;
    while (bj * (bj + 1) / 2 > idx) bj--;
    int bi = idx - bj * (bj + 1) / 2;
    int rowA = bi * 128, rowB = bj * 128;

    // ---- stage loader: 2048 x 16B per stage, 16 per thread -------------------
    // rows of 128B (8 chunks); chunk c of row r stored at slot c ^ (r&7)
    auto load_stage = [&](int kt, int slot) {
#pragma unroll
        for (int i = 0; i < 16; i++) {
            int t = tid + i * 128;
            int isA = (t < 1024);
            int u = t & 1023;
            int r = u >> 3;
            int c16 = u & 7;
            int grow = (isA ? rowA : rowB) + r;
            const __nv_bfloat16* gp = g_data + (size_t)grow * 512 + kt * 64 + c16 * 8;
            uint32_t off = r * 128 + ((c16 ^ (r & 7)) << 4);
            uint32_t sa = sbase + slot * STAGE_BYTES + (isA ? 0 : A_BYTES) + off;
            cp_async16(sa, gp);
        }
        CP_COMMIT();
    };

    load_stage(0, 0);
    load_stage(1, 1);

    int wm = (wid >> 1) * 64;   // warp m offset (0 or 64)
    int wn = (wid & 1) * 64;    // warp n offset (0 or 64)

    // ldmatrix lane decomposition
    int mat = lane >> 3, r8 = lane & 7;
    int lrow = (mat & 1) * 8 + r8;
    int lhi  = mat >> 1;

    // base ldmatrix offsets for ks=0; addr(ks) = stg + (off0 ^ (ks<<5))
    uint32_t aoff0[4], boff0[4];
#pragma unroll
    for (int mt = 0; mt < 4; mt++) {
        int m = wm + mt * 16 + lrow;
        aoff0[mt] = m * 128 + ((lhi ^ (m & 7)) << 4);
    }
#pragma unroll
    for (int g = 0; g < 4; g++) {
        int n = wn + g * 16 + lrow;
        boff0[g] = A_BYTES + n * 128 + ((lhi ^ (n & 7)) << 4);
    }

    float acc[4][8][4];
#pragma unroll
    for (int a = 0; a < 4; a++)
#pragma unroll
        for (int b = 0; b < 8; b++)
#pragma unroll
            for (int c = 0; c < 4; c++) acc[a][b][c] = 0.f;

    for (int kt = 0; kt < KT; kt++) {
        int slot = kt % 3;
        CP_WAIT1();
        __syncthreads();
        if (kt + 2 < KT) load_stage(kt + 2, (kt + 2) % 3);
        else { CP_COMMIT(); }

        uint32_t stg = sbase + slot * STAGE_BYTES;

#pragma unroll
        for (int ks = 0; ks < 4; ks++) {
            uint32_t kx = (uint32_t)(ks << 5);
            uint32_t af[4][4], bf[4][4];
#pragma unroll
            for (int mt = 0; mt < 4; mt++)
                ldsm4(af[mt][0], af[mt][1], af[mt][2], af[mt][3],
                      stg + (aoff0[mt] ^ kx));
#pragma unroll
            for (int g = 0; g < 4; g++)
                ldsm4(bf[g][0], bf[g][1], bf[g][2], bf[g][3],
                      stg + (boff0[g] ^ kx));
#pragma unroll
            for (int mt = 0; mt < 4; mt++)
#pragma unroll
                for (int nt = 0; nt < 8; nt++)
                    hmma(acc[mt][nt], af[mt],
                         bf[nt >> 1][nt & 1], bf[nt >> 1][(nt & 1) + 2]);
        }
    }
    __syncthreads();   // all compute done before epilogue reuses smem

    // ---- epilogue ------------------------------------------------------------
    float* s_sq = (float*)sm;          // [0:128)=A rows, [128:256)=B rows
    s_sq[tid] = g_sq[rowA + tid];
    s_sq[tid + 128] = g_sq[rowB + tid];
    __syncthreads();

    float cc = g_cc;
    int er = lane >> 2, ec = (lane & 3) * 2;
    double dsum = 0.0;
#pragma unroll
    for (int mt = 0; mt < 4; mt++) {
        float sqi0 = s_sq[wm + mt * 16 + er];
        float sqi1 = s_sq[wm + mt * 16 + er + 8];
#pragma unroll
        for (int nt = 0; nt < 8; nt++) {
            float sqj0 = s_sq[128 + wn + nt * 8 + ec];
            float sqj1 = s_sq[128 + wn + nt * 8 + ec + 1];
            float d0 = acc[mt][nt][0], d1 = acc[mt][nt][1];
            float d2 = acc[mt][nt][2], d3 = acc[mt][nt][3];
            float l0 = fmaxf(fmaf(-2.f, d0, sqi0 + sqj0), 0.f);
            float l1 = fmaxf(fmaf(-2.f, d1, sqi0 + sqj1), 0.f);
            float l2 = fmaxf(fmaf(-2.f, d2, sqi1 + sqj0), 0.f);
            float l3 = fmaxf(fmaf(-2.f, d3, sqi1 + sqj1), 0.f);
            float t0 = ex2f(l0 * cc), t1 = ex2f(l1 * cc);
            float t2 = ex2f(l2 * cc), t3 = ex2f(l3 * cc);
            float fs = 0.f;
            {
                float a2 = t0 * t0, a4 = a2 * a2, a8 = a4 * a4;
                fs += ((t0 + a2) + (a4 + a8)) + a8 * a8;
            }
            {
                float a2 = t1 * t1, a4 = a2 * a2, a8 = a4 * a4;
                fs += ((t1 + a2) + (a4 + a8)) + a8 * a8;
            }
            {
                float a2 = t2 * t2, a4 = a2 * a2, a8 = a4 * a4;
                fs += ((t2 + a2) + (a4 + a8)) + a8 * a8;
            }
            {
                float a2 = t3 * t3, a4 = a2 * a2, a8 = a4 * a4;
                fs += ((t3 + a2) + (a4 + a8)) + a8 * a8;
            }
            dsum += (double)fs;
        }
    }

    // block reduce doubles in smem
    __syncthreads();
    double* red = (double*)sm;
    red[tid] = dsum;
    __syncthreads();
    for (int o = 64; o; o >>= 1) { if (tid < o) red[tid] += red[tid + o]; __syncthreads(); }
    if (tid == 0) {
        int hi = (bi >= 32), hj = (bj >= 32);
        atomicAdd(&g_acc[hi * 2 + hj], red[0]);
        if (bi != bj) atomicAdd(&g_acc[hj * 2 + hi], red[0]);
    }
}

// ---------------- kernel 4: final scalar ------------------------------------
__global__ void k_final(float* __restrict__ out) {
    double inv = 1.0 / (4096.0 * 4096.0);
    out[0] = (float)((g_acc[0] + g_acc[3] - g_acc[1] - g_acc[2]) * inv);
}

// ---------------- launcher ---------------------------------------------------
extern "C" void kernel_launch(void* const* d_in, const int* in_sizes, int n_in,
                              void* d_out, int out_size) {
    const float* src = (const float*)d_in[0];
    const float* tgt = (const float*)d_in[1];
    float* out = (float*)d_out;

    cudaFuncSetAttribute(k_mma, cudaFuncAttributeMaxDynamicSharedMemorySize, SMEM_TOTAL);

    k_zero<<<2, 256>>>();
    k_prep<<<256, 256>>>(src, tgt);
    k_scale<<<1, 512>>>();
    k_mma<<<2080, 128, SMEM_TOTAL>>>();
    k_final<<<1, 1>>>(out);
}

// round 8
// speedup vs baseline: 1.4776x; 1.0161x over previous
#include <cuda_runtime.h>
#include <cuda_fp16.h>
#include <math.h>
#include <stdint.h>

typedef unsigned long long ull;

// ---------------- device globals (scratch; no allocations allowed) ----------
__device__ __half  g_data[8192 * 512]; // fp16 concatenated [source; target]
__device__ float   g_sq[8192];         // per-row squared L2 norms (fp32)
__device__ float   g_colpart[256][512];// per-block column sums
__device__ double  g_sqpart[256];      // per-block sq-norm sums
__device__ int     g_done;             // completion counter (self-resetting)
__device__ double  g_acc[4];           // quadrant sums [XX, XY, YX, YY]
__device__ float   g_cc;               // -log2(e) / (bw * 16)

// ---------------- PTX helpers ----------------------------------------------
__device__ __forceinline__ float ex2f(float x) {
    float y; asm("ex2.approx.ftz.f32 %0, %1;" : "=f"(y) : "f"(x)); return y;
}
__device__ __forceinline__ uint32_t smem_u32(const void* p) {
    uint32_t a;
    asm("{ .reg .u64 t; cvta.to.shared.u64 t, %1; cvt.u32.u64 %0, t; }" : "=r"(a) : "l"(p));
    return a;
}
__device__ __forceinline__ void cp_async16(uint32_t saddr, const void* g) {
    asm volatile("cp.async.cg.shared.global [%0], [%1], 16;" :: "r"(saddr), "l"(g));
}
#define CP_COMMIT()  asm volatile("cp.async.commit_group;" ::: "memory")
#define CP_WAIT1()   asm volatile("cp.async.wait_group 1;" ::: "memory")

__device__ __forceinline__ void ldsm4(uint32_t& r0, uint32_t& r1, uint32_t& r2,
                                      uint32_t& r3, uint32_t addr) {
    asm volatile("ldmatrix.sync.aligned.m8n8.x4.shared.b16 {%0,%1,%2,%3}, [%4];"
                 : "=r"(r0), "=r"(r1), "=r"(r2), "=r"(r3) : "r"(addr));
}
__device__ __forceinline__ void hmma(float* d, const uint32_t* a, uint32_t b0, uint32_t b1) {
    asm volatile(
        "mma.sync.aligned.m16n8k16.row.col.f32.f16.f16.f32 "
        "{%0,%1,%2,%3}, {%4,%5,%6,%7}, {%8,%9}, {%0,%1,%2,%3};"
        : "+f"(d[0]), "+f"(d[1]), "+f"(d[2]), "+f"(d[3])
        : "r"(a[0]), "r"(a[1]), "r"(a[2]), "r"(a[3]), "r"(b0), "r"(b1));
}

// ---------------- kernel 1: fused prep + finalize ---------------------------
// grid 256 x 256 threads; 32 rows per block. Partials, last block finalizes:
// computes bandwidth coefficient, zeroes g_acc, resets counter.
__global__ __launch_bounds__(256)
void k_prep(const float* __restrict__ src, const float* __restrict__ tgt) {
    __shared__ float  scol[512];
    __shared__ double ssq[8];
    __shared__ double sred[256];
    __shared__ int    s_last;
    int tid = threadIdx.x, w = tid >> 5, lane = tid & 31;

    for (int i = tid; i < 512; i += 256) scol[i] = 0.f;

    float colacc[16];
#pragma unroll
    for (int i = 0; i < 16; i++) colacc[i] = 0.f;

    double warp_sq = 0.0;
    __syncthreads();

#pragma unroll
    for (int rr = 0; rr < 4; rr++) {
        int row = blockIdx.x * 32 + w * 4 + rr;
        const float* p = (row < 4096) ? src + (size_t)row * 512
                                      : tgt + (size_t)(row - 4096) * 512;
        float s = 0.f;
#pragma unroll
        for (int c = 0; c < 4; c++) {
            float4 v = *(const float4*)(p + lane * 4 + c * 128);
            uint2 o;
            asm("cvt.rn.f16x2.f32 %0, %1, %2;" : "=r"(o.x) : "f"(v.y), "f"(v.x));
            asm("cvt.rn.f16x2.f32 %0, %1, %2;" : "=r"(o.y) : "f"(v.w), "f"(v.z));
            *(uint2*)(g_data + (size_t)row * 512 + lane * 4 + c * 128) = o;
            s = fmaf(v.x, v.x, s); s = fmaf(v.y, v.y, s);
            s = fmaf(v.z, v.z, s); s = fmaf(v.w, v.w, s);
            colacc[c * 4 + 0] += v.x; colacc[c * 4 + 1] += v.y;
            colacc[c * 4 + 2] += v.z; colacc[c * 4 + 3] += v.w;
        }
#pragma unroll
        for (int o = 16; o; o >>= 1) s += __shfl_xor_sync(0xffffffffu, s, o);
        if (lane == 0) { g_sq[row] = s; warp_sq += (double)s; }
    }

#pragma unroll
    for (int c = 0; c < 4; c++)
#pragma unroll
        for (int j = 0; j < 4; j++)
            atomicAdd(&scol[lane * 4 + c * 128 + j], colacc[c * 4 + j]);
    if (lane == 0) ssq[w] = warp_sq;
    __syncthreads();

    for (int i = tid; i < 512; i += 256) g_colpart[blockIdx.x][i] = scol[i];
    if (tid == 0) {
        double t = 0;
        for (int i = 0; i < 8; i++) t += ssq[i];
        g_sqpart[blockIdx.x] = t;
        __threadfence();
        s_last = (atomicAdd(&g_done, 1) == 255);
    }
    __syncthreads();
    if (!s_last) return;

    // ---- last block: finalize bandwidth ----
    __threadfence();
    double csq = 0.0;
    for (int d = tid; d < 512; d += 256) {
        float c0 = 0.f, c1 = 0.f, c2 = 0.f, c3 = 0.f;
        for (int b = 0; b < 256; b += 4) {
            c0 += g_colpart[b + 0][d];
            c1 += g_colpart[b + 1][d];
            c2 += g_colpart[b + 2][d];
            c3 += g_colpart[b + 3][d];
        }
        double c = (double)((c0 + c1) + (c2 + c3));
        csq += c * c;
    }
    sred[tid] = csq;
    __syncthreads();
    for (int o = 128; o; o >>= 1) { if (tid < o) sred[tid] += sred[tid + o]; __syncthreads(); }
    double csq_tot = sred[0];
    __syncthreads();
    sred[tid] = g_sqpart[tid];
    __syncthreads();
    for (int o = 128; o; o >>= 1) { if (tid < o) sred[tid] += sred[tid + o]; __syncthreads(); }
    if (tid == 0) {
        double n = 8192.0;
        double sum_l2 = 2.0 * n * sred[0] - 2.0 * csq_tot;
        double bw = sum_l2 / (n * n - n);
        bw /= 4.0;  // KERNEL_MUL ** (KERNEL_NUM // 2)
        const double LOG2E = 1.4426950408889634;
        g_cc = (float)(-LOG2E / (bw * 16.0));
        g_acc[0] = g_acc[1] = g_acc[2] = g_acc[3] = 0.0;
        g_done = 0;
    }
}

// ---------------- kernel 2: mma.sync fp16 GEMM + fused epilogue -------------
// CTA tile 128x128, triangular over 64x64 blocks -> 2080 CTAs.
// 4 warps (2m x 2n), warp tile 64x64, 128 threads, 2 CTAs/SM.
// K=512 in 8 chunks of 64 (4 ks phases), 3-stage cp.async pipeline.
static constexpr int KT = 8;
static constexpr int A_BYTES = 16384;       // 128 rows x 128B
static constexpr int STAGE_BYTES = 32768;   // A 16KB + B 16KB
static constexpr int SMEM_TOTAL = 3 * STAGE_BYTES;  // 98304

__global__ __launch_bounds__(128, 2)
void k_mma() {
    extern __shared__ char sm[];
    uint32_t sbase = smem_u32(sm);

    int tid = threadIdx.x;
    int wid = tid >> 5, lane = tid & 31;

    // triangular block decode: idx = bj*(bj+1)/2 + bi, bi <= bj (64 blocks)
    int idx = blockIdx.x;
    int bj = (int)((sqrtf(8.0f * (float)idx + 1.0f) - 1.0f) * 0.5f);
    while ((bj + 1) * (bj + 2) / 2 <= idx) bj++;
    while (bj * (bj + 1) / 2 > idx) bj--;
    int bi = idx - bj * (bj + 1) / 2;
    int rowA = bi * 128, rowB = bj * 128;

    // ---- strength-reduced stage loader --------------------------------------
    // per thread: fixed column group c16 = tid&7, base row r0 = tid>>3;
    // i-th load covers row r0+16i; swizzle slot constant across i and kt.
    int r0 = tid >> 3, c16 = tid & 7;
    uint32_t soff = (uint32_t)(r0 * 128 + ((c16 ^ (r0 & 7)) << 4));
    const __half* gA = g_data + (size_t)(rowA + r0) * 512 + c16 * 8;
    const __half* gB = g_data + (size_t)(rowB + r0) * 512 + c16 * 8;

    auto load_stage = [&](int kt, uint32_t stg) {
        const __half* pa = gA + kt * 64;
        const __half* pb = gB + kt * 64;
#pragma unroll
        for (int i = 0; i < 8; i++)
            cp_async16(stg + soff + i * 2048, pa + i * 8192);
#pragma unroll
        for (int i = 0; i < 8; i++)
            cp_async16(stg + A_BYTES + soff + i * 2048, pb + i * 8192);
        CP_COMMIT();
    };

    load_stage(0, sbase);
    load_stage(1, sbase + STAGE_BYTES);

    int wm = (wid >> 1) * 64;   // warp m offset
    int wn = (wid & 1) * 64;    // warp n offset

    // ldmatrix lane decomposition
    int mat = lane >> 3, r8 = lane & 7;
    int lrow = (mat & 1) * 8 + r8;
    int lhi  = mat >> 1;

    // base ldmatrix offsets (ks=0); addr(ks) = stg + (off0 ^ (ks<<5))
    uint32_t aoff0[4], boff0[4];
#pragma unroll
    for (int mt = 0; mt < 4; mt++) {
        int m = wm + mt * 16 + lrow;
        aoff0[mt] = m * 128 + ((lhi ^ (m & 7)) << 4);
    }
#pragma unroll
    for (int g = 0; g < 4; g++) {
        int n = wn + g * 16 + lrow;
        boff0[g] = A_BYTES + n * 128 + ((lhi ^ (n & 7)) << 4);
    }

    // ks phase stagger: co-resident CTAs (adjacent waves) start 2 apart
    int ksoff = ((blockIdx.x / 148) & 1) * 2;

    float acc[4][8][4];
#pragma unroll
    for (int a = 0; a < 4; a++)
#pragma unroll
        for (int b = 0; b < 8; b++)
#pragma unroll
            for (int c = 0; c < 4; c++) acc[a][b][c] = 0.f;

    uint32_t af[4][4], bf[4][4];

    auto frag_load = [&](uint32_t stg, int ksx) {
        uint32_t kx = (uint32_t)(ksx << 5);
#pragma unroll
        for (int mt = 0; mt < 4; mt++)
            ldsm4(af[mt][0], af[mt][1], af[mt][2], af[mt][3], stg + (aoff0[mt] ^ kx));
#pragma unroll
        for (int g = 0; g < 4; g++)
            ldsm4(bf[g][0], bf[g][1], bf[g][2], bf[g][3], stg + (boff0[g] ^ kx));
    };
    auto frag_mma = [&]() {
#pragma unroll
        for (int mt = 0; mt < 4; mt++)
#pragma unroll
            for (int nt = 0; nt < 8; nt++)
                hmma(acc[mt][nt], af[mt],
                     bf[nt >> 1][nt & 1], bf[nt >> 1][(nt & 1) + 2]);
    };

    uint32_t stg_c = sbase;                      // compute slot (kt)
    uint32_t stg_n = sbase + STAGE_BYTES;        // next slot (kt+1)
    uint32_t stg_l = sbase + 2 * STAGE_BYTES;    // load target (kt+2)

    for (int kt = 0; kt < KT; kt++) {
        CP_WAIT1();
        __syncthreads();

        frag_load(stg_c, ksoff);                 // first phase frags first
        if (kt + 2 < KT) load_stage(kt + 2, stg_l);
        else { CP_COMMIT(); }
        frag_mma();

#pragma unroll
        for (int s = 1; s < 4; s++) {
            frag_load(stg_c, (s + ksoff) & 3);
            frag_mma();
        }

        uint32_t t = stg_c; stg_c = stg_n; stg_n = stg_l; stg_l = t;
    }
    __syncthreads();   // all compute done before epilogue reuses smem

    // ---- epilogue ------------------------------------------------------------
    float* s_sq = (float*)sm;                    // [0:128)=A rows, [128:256)=B rows
    double* sred = (double*)(sm + 1024);
    s_sq[tid] = g_sq[rowA + tid];
    s_sq[tid + 128] = g_sq[rowB + tid];
    __syncthreads();

    float cc = g_cc;
    int er = lane >> 2, ec = (lane & 3) * 2;
    float fsum = 0.f;
#pragma unroll
    for (int mt = 0; mt < 4; mt++) {
        float sqi0 = s_sq[wm + mt * 16 + er];
        float sqi1 = s_sq[wm + mt * 16 + er + 8];
#pragma unroll
        for (int nt = 0; nt < 8; nt++) {
            float sqj0 = s_sq[128 + wn + nt * 8 + ec];
            float sqj1 = s_sq[128 + wn + nt * 8 + ec + 1];
            float d0 = acc[mt][nt][0], d1 = acc[mt][nt][1];
            float d2 = acc[mt][nt][2], d3 = acc[mt][nt][3];
            float l0 = fmaxf(fmaf(-2.f, d0, sqi0 + sqj0), 0.f);
            float l1 = fmaxf(fmaf(-2.f, d1, sqi0 + sqj1), 0.f);
            float l2 = fmaxf(fmaf(-2.f, d2, sqi1 + sqj0), 0.f);
            float l3 = fmaxf(fmaf(-2.f, d3, sqi1 + sqj1), 0.f);
            float t0 = ex2f(l0 * cc), t1 = ex2f(l1 * cc);
            float t2 = ex2f(l2 * cc), t3 = ex2f(l3 * cc);
            {
                float a2 = t0 * t0, a4 = a2 * a2, a8 = a4 * a4;
                fsum += ((t0 + a2) + (a4 + a8)) + a8 * a8;
            }
            {
                float a2 = t1 * t1, a4 = a2 * a2, a8 = a4 * a4;
                fsum += ((t1 + a2) + (a4 + a8)) + a8 * a8;
            }
            {
                float a2 = t2 * t2, a4 = a2 * a2, a8 = a4 * a4;
                fsum += ((t2 + a2) + (a4 + a8)) + a8 * a8;
            }
            {
                float a2 = t3 * t3, a4 = a2 * a2, a8 = a4 * a4;
                fsum += ((t3 + a2) + (a4 + a8)) + a8 * a8;
            }
        }
    }

    // warp shuffle reduce (float), then 4 doubles in smem
#pragma unroll
    for (int o = 16; o; o >>= 1) fsum += __shfl_xor_sync(0xffffffffu, fsum, o);
    if (lane == 0) sred[wid] = (double)fsum;
    __syncthreads();
    if (tid == 0) {
        double tot = (sred[0] + sred[1]) + (sred[2] + sred[3]);
        int hi = (bi >= 32), hj = (bj >= 32);
        atomicAdd(&g_acc[hi * 2 + hj], tot);
        if (bi != bj) atomicAdd(&g_acc[hj * 2 + hi], tot);
    }
}

// ---------------- kernel 3: final scalar ------------------------------------
__global__ void k_final(float* __restrict__ out) {
    double inv = 1.0 / (4096.0 * 4096.0);
    out[0] = (float)((g_acc[0] + g_acc[3] - g_acc[1] - g_acc[2]) * inv);
}

// ---------------- launcher ---------------------------------------------------
extern "C" void kernel_launch(void* const* d_in, const int* in_sizes, int n_in,
                              void* d_out, int out_size) {
    const float* src = (const float*)d_in[0];
    const float* tgt = (const float*)d_in[1];
    float* out = (float*)d_out;

    cudaFuncSetAttribute(k_mma, cudaFuncAttributeMaxDynamicSharedMemorySize, SMEM_TOTAL);

    k_prep<<<256, 256>>>(src, tgt);
    k_mma<<<2080, 128, SMEM_TOTAL>>>();
    k_final<<<1, 1>>>(out);
}